// round 13
// baseline (speedup 1.0000x reference)
#include <cuda_runtime.h>
#include <math.h>
#include <stdint.h>

// ---------------------------------------------------------------------------
// VQ-VAE VectorQuantizer forward — single persistent kernel.
// R13 (= R12 resubmit; infra failed before execution): 148 CTAs x 512 threads
// (1/SM), thread tile 8px x 4codes -> acc fits in registers (no spills).
// Same math/merge/reset as the passing R10 kernel.
//   out = [ z_q_st (2097152) | vq_loss | indices (32768) | perplexity | usage (1024) ]
// ---------------------------------------------------------------------------

#define D_DIM   64
#define KCODES  1024
#define HW      1024
#define TM      128
#define KC      128
#define NPT     256                 // pixel tiles
#define QTOT    2048                // 256 tiles x 8 chunks
#define NCTA    148                 // 1 per SM
#define NTHR    512

#define OFS_LOSS  2097152
#define OFS_IDX   2097153
#define OFS_PPL   2129921
#define OFS_USAGE 2129922

__device__ int                g_counts[KCODES];      // zero-init; reset by finisher
__device__ float              g_sse;
__device__ int                g_done[NPT];
__device__ int                g_tiles_done;
__device__ unsigned long long g_best[NPT * TM];      // ~((dist_bits<<32)|k); 0 = identity

// ---- packed f32x2 helpers --------------------------------------------------
__device__ __forceinline__ unsigned long long pack2(float x, float y) {
    unsigned long long r;
    asm("mov.b64 %0, {%1, %2};" : "=l"(r) : "f"(x), "f"(y));
    return r;
}
__device__ __forceinline__ void fma2(unsigned long long& d,
                                     unsigned long long a,
                                     unsigned long long b) {
    asm("fma.rn.f32x2 %0, %1, %2, %0;" : "+l"(d) : "l"(a), "l"(b));
}
__device__ __forceinline__ float2 unpack2(unsigned long long v) {
    float2 f;
    asm("mov.b64 {%0, %1}, %2;" : "=f"(f.x), "=f"(f.y) : "l"(v));
    return f;
}

struct Sm {
    float z_s[D_DIM][TM + 4];     // 33792 B : z tile [d][p]
    float e_s[D_DIM][KC + 4];     // 33792 B : chunk [d][k]; zq stage aliases
    float e2c[KC];                //   512 B
    float z2_s[TM];               //   512 B
    float red_d[16][TM];          //  8192 B
    int   red_i[16][TM];          //  8192 B
    int   idx_s[TM];              //   512 B
    int   cnt_s[KCODES];          //  4096 B
    int   flag, flag2;
};                                 // ~89.6 KB

// ---------------------------------------------------------------------------
// finalize (usage / perplexity / loss) + module-state reset — once per launch
// ---------------------------------------------------------------------------
__device__ __noinline__ void vq_finalize(Sm* sm, float* __restrict__ out,
                                         int tid) {
    __threadfence();
    float hpart = 0.f;
    for (int i = tid; i < KCODES; i += NTHR) {
        int c = *((volatile int*)&g_counts[i]);
        float u = (float)c / 32768.0f;
        out[OFS_USAGE + i] = u;
        hpart += u * logf(u + 1e-10f);
    }
#pragma unroll
    for (int o = 16; o; o >>= 1)
        hpart += __shfl_xor_sync(0xffffffffu, hpart, o);
    if ((tid & 31) == 0) sm->red_d[0][tid >> 5] = hpart;
    __syncthreads();
    if (tid == 0) {
        float H = 0.f;
#pragma unroll
        for (int w2 = 0; w2 < 16; ++w2) H += sm->red_d[0][w2];
        out[OFS_PPL] = expf(-H);
        float msse = *((volatile float*)&g_sse);
        float m = msse / 2097152.0f;
        out[OFS_LOSS] = m + 0.25f * m;
    }
    __syncthreads();
    // reset module state for next graph replay
    for (int i = tid; i < KCODES; i += NTHR) g_counts[i] = 0;
    for (int i = tid; i < NPT; i += NTHR)    g_done[i] = 0;
    for (int i = tid; i < NPT * TM; i += NTHR) g_best[i] = 0ull;
    if (tid == 0) { g_sse = 0.f; g_tiles_done = 0; }
}

// ---------------------------------------------------------------------------
// tile epilogue — runs in the CTA that completes a tile's 8th chunk
// ---------------------------------------------------------------------------
__device__ __noinline__ void vq_tile_epilogue(Sm* sm, const float* __restrict__ cb,
                                              float* __restrict__ out,
                                              int tid, int cur_tile, int b, int hw0) {
    __threadfence();
    for (int i = tid; i < KCODES; i += NTHR) sm->cnt_s[i] = 0;
    __syncthreads();
    if (tid < TM) {
        unsigned long long raw =
            *((volatile unsigned long long*)&g_best[cur_tile * TM + tid]);
        int bi = (int)(unsigned)((~raw) & 0xFFFFFFFFull);
        sm->idx_s[tid] = bi;
        out[OFS_IDX + cur_tile * TM + tid] = (float)bi;
        atomicAdd(&sm->cnt_s[bi], 1);
    }
    __syncthreads();
    for (int i = tid; i < KCODES; i += NTHR) {
        int c = sm->cnt_s[i];
        if (c) atomicAdd(&g_counts[i], c);
    }
    {   // gather z_q, z_q_st (reference two roundings), SSE; 4 threads/pixel
        int p = tid >> 2, qq = tid & 3;
        int ci = sm->idx_s[p];
        const float4* crow = reinterpret_cast<const float4*>(
                                 cb + (size_t)ci * D_DIM) + qq * 4;
        float ssel = 0.f;
#pragma unroll
        for (int i = 0; i < 4; ++i) {
            float4 v = crow[i];
            int d0 = qq * 16 + i * 4;
            float vv[4] = {v.x, v.y, v.z, v.w};
#pragma unroll
            for (int cc = 0; cc < 4; ++cc) {
                int d = d0 + cc;
                float zev  = sm->z_s[d][p];
                float diff = vv[cc] - zev;       // fl(z_q - z_e)
                ssel = fmaf(diff, diff, ssel);
                sm->e_s[d][p] = zev + diff;      // fl(z_e + diff)
            }
        }
#pragma unroll
        for (int o = 16; o; o >>= 1)
            ssel += __shfl_xor_sync(0xffffffffu, ssel, o);
        if ((tid & 31) == 0) atomicAdd(&g_sse, ssel);
    }
    __syncthreads();
    {   // coalesced z_q_st store
        float* zo = out + (size_t)b * D_DIM * HW + hw0;
        for (int f = tid; f < D_DIM * TM; f += NTHR) {
            int d = f >> 7, p = f & 127;
            zo[d * HW + p] = sm->e_s[d][p];
        }
    }
    __threadfence();
    if (tid == 0)
        sm->flag2 = (atomicAdd(&g_tiles_done, 1) == NPT - 1);
    __syncthreads();
    if (sm->flag2) vq_finalize(sm, out, tid);
}

// ---------------------------------------------------------------------------
// main persistent kernel
// ---------------------------------------------------------------------------
__global__ void __launch_bounds__(NTHR, 1)
vq_all(const float* __restrict__ ze, const float* __restrict__ cb,
       float* __restrict__ out) {
    extern __shared__ __align__(16) char smem_raw[];
    Sm* sm = reinterpret_cast<Sm*>(smem_raw);

    const int tid = threadIdx.x;
    const int q0  = (blockIdx.x * QTOT) / NCTA;
    const int q1  = ((blockIdx.x + 1) * QTOT) / NCTA;

    const int pcol  = tid & 15;          // 16 pixel columns x 8 px
    const int krow  = tid >> 4;          // 32 code rows x 4 codes
    const int p0    = pcol * 8;
    const int kloc0 = krow * 4;
    const int k_st  = tid & 127;         // staging: warp-per-d-range, conflict-free
    const int h_st  = tid >> 7;          // 0..3 quarter of d

    int   cur_tile = -1, seg_chunks = 0, b = 0, hw0 = 0;
    float z2r[8];
    float bestd[8];
    int   besti[8];

    for (int q = q0;; ++q) {
        const int tile = (q < q1) ? (q >> 3) : -1;

        if (tile != cur_tile) {
            if (cur_tile >= 0) {
                // ---- segment flush: merge bests into g_best ----------------
                // shfl 16 merges krow pair (2w, 2w+1): partner has higher k
#pragma unroll
                for (int j = 0; j < 8; ++j) {
                    float od = __shfl_xor_sync(0xffffffffu, bestd[j], 16);
                    int   oi = __shfl_xor_sync(0xffffffffu, besti[j], 16);
                    if (od < bestd[j] || (od == bestd[j] && oi < besti[j])) {
                        bestd[j] = od; besti[j] = oi;
                    }
                }
                const int w = tid >> 5;              // 0..15
                if ((tid & 16) == 0) {
#pragma unroll
                    for (int j = 0; j < 8; ++j) {
                        sm->red_d[w][p0 + j] = bestd[j];
                        sm->red_i[w][p0 + j] = besti[j];
                    }
                }
                __syncthreads();
                if (tid < TM) {
                    float bd = sm->red_d[0][tid];
                    int   bi = sm->red_i[0][tid];
#pragma unroll
                    for (int w2 = 1; w2 < 16; ++w2) {   // ascending k
                        float d2 = sm->red_d[w2][tid];
                        int   i2 = sm->red_i[w2][tid];
                        if (d2 < bd || (d2 == bd && i2 < bi)) { bd = d2; bi = i2; }
                    }
                    // dist strictly > 0 -> float bits are order-preserving
                    unsigned long long pk =
                        ((unsigned long long)__float_as_uint(bd) << 32) | (unsigned)bi;
                    atomicMax(&g_best[cur_tile * TM + tid], ~pk);
                }
                __threadfence();
                if (tid == 0)
                    sm->flag = (atomicAdd(&g_done[cur_tile], seg_chunks)
                                + seg_chunks == 8);
                __syncthreads();
                if (sm->flag)
                    vq_tile_epilogue(sm, cb, out, tid, cur_tile, b, hw0);
                __syncthreads();   // epilogue done before z_s is overwritten
            }
            if (tile < 0) break;

            // ---- load new tile --------------------------------------------
            cur_tile  = tile;
            seg_chunks = 0;
            b   = tile >> 3;
            hw0 = (tile & 7) * TM;
            const float* zbase = ze + (size_t)b * D_DIM * HW + hw0;
            for (int f = tid; f < D_DIM * TM; f += NTHR) {
                int d = f >> 7, p = f & 127;
                sm->z_s[d][p] = zbase[d * HW + p];
            }
            __syncthreads();
            if (tid < TM) {                          // reference rounding
                float s = 0.f;
#pragma unroll
                for (int d = 0; d < D_DIM; ++d) {
                    float v = sm->z_s[d][tid];
                    s = fmaf(v, v, s);
                }
                sm->z2_s[tid] = s;
            }
            __syncthreads();
#pragma unroll
            for (int j = 0; j < 8; ++j) z2r[j] = sm->z2_s[p0 + j];
#pragma unroll
            for (int j = 0; j < 8; ++j) { bestd[j] = 3.4e38f; besti[j] = 0; }
        }

        // ---- process one chunk --------------------------------------------
        const int kb = (q & 7) * KC;

        {   // stage codebook chunk transposed [d][k] (conflict-free STS)
            const float4* src = reinterpret_cast<const float4*>(
                                    cb + (size_t)(kb + k_st) * D_DIM) + h_st * 4;
#pragma unroll
            for (int i = 0; i < 4; ++i) {
                float4 v = src[i];
                int d0 = h_st * 16 + i * 4;
                sm->e_s[d0 + 0][k_st] = v.x;
                sm->e_s[d0 + 1][k_st] = v.y;
                sm->e_s[d0 + 2][k_st] = v.z;
                sm->e_s[d0 + 3][k_st] = v.w;
            }
        }
        __syncthreads();
        if (tid < KC) {                              // inline e2, reference order
            float s = 0.f;
#pragma unroll
            for (int d = 0; d < D_DIM; ++d) {
                float v = sm->e_s[d][tid];
                s = fmaf(v, v, s);
            }
            sm->e2c[tid] = s;
        }
        __syncthreads();

        unsigned long long acc[8][2];                // 8 px x 4 codes
#pragma unroll
        for (int j = 0; j < 8; ++j) { acc[j][0] = 0ull; acc[j][1] = 0ull; }

#pragma unroll 16
        for (int d = 0; d < D_DIM; ++d) {
            ulonglong2 eA = *reinterpret_cast<const ulonglong2*>(&sm->e_s[d][kloc0]);
            float4 za = *reinterpret_cast<const float4*>(&sm->z_s[d][p0]);
            float4 zb = *reinterpret_cast<const float4*>(&sm->z_s[d][p0 + 4]);
            float zr[8] = {za.x, za.y, za.z, za.w, zb.x, zb.y, zb.z, zb.w};
#pragma unroll
            for (int j = 0; j < 8; ++j) {
                unsigned long long zz = pack2(zr[j], zr[j]);
                fma2(acc[j][0], zz, eA.x);
                fma2(acc[j][1], zz, eA.y);
            }
        }

        float e2r[4];
#pragma unroll
        for (int kk = 0; kk < 4; ++kk) e2r[kk] = sm->e2c[kloc0 + kk];
#pragma unroll
        for (int j = 0; j < 8; ++j) {
            float a = z2r[j];
#pragma unroll
            for (int kk = 0; kk < 2; ++kk) {
                float2 s = unpack2(acc[j][kk]);
                float d0 = fmaf(-2.f, s.x, a + e2r[kk * 2]);
                float d1 = fmaf(-2.f, s.y, a + e2r[kk * 2 + 1]);
                int k0 = kb + kloc0 + kk * 2;
                if (d0 < bestd[j]) { bestd[j] = d0; besti[j] = k0; }
                if (d1 < bestd[j]) { bestd[j] = d1; besti[j] = k0 + 1; }
            }
        }
        ++seg_chunks;
        __syncthreads();   // all reads of e_s done before next stage/epilogue
    }
}

// ---------------------------------------------------------------------------
extern "C" void kernel_launch(void* const* d_in, const int* in_sizes, int n_in,
                              void* d_out, int out_size) {
    const float* a0 = (const float*)d_in[0];
    const float* a1 = (const float*)d_in[1];
    const float* ze = a0;
    const float* cb = a1;
    if (n_in >= 2 && in_sizes[0] == KCODES * D_DIM) { ze = a1; cb = a0; }
    float* out = (float*)d_out;

    static_assert(sizeof(Sm) < 100 * 1024, "smem too big");
    cudaFuncSetAttribute(vq_all, cudaFuncAttributeMaxDynamicSharedMemorySize,
                         (int)sizeof(Sm));
    vq_all<<<NCTA, NTHR, sizeof(Sm)>>>(ze, cb, out);
}

// round 14
// speedup vs baseline: 1.5095x; 1.5095x over previous
#include <cuda_runtime.h>
#include <math.h>
#include <stdint.h>

// ---------------------------------------------------------------------------
// VQ-VAE VectorQuantizer forward — single persistent kernel (R10 skeleton).
// R14: warp-geometry remap 16x2 -> 8x4 (pcol x krow per warp). Same thread
// tile (8px x 8codes), same instructions; z-LDS wavefronts halve via
// broadcast dedup -> L1tex (the measured binding unit) drops ~33%.
//   out = [ z_q_st (2097152) | vq_loss | indices (32768) | perplexity | usage (1024) ]
// ---------------------------------------------------------------------------

#define D_DIM   64
#define KCODES  1024
#define HW      1024
#define TM      128
#define KC      128
#define NPT     256                 // pixel tiles
#define QTOT    2048                // 256 tiles x 8 chunks
#define NCTA    296                 // 2 per SM on 148 SMs

#define OFS_LOSS  2097152
#define OFS_IDX   2097153
#define OFS_PPL   2129921
#define OFS_USAGE 2129922

__device__ int                g_counts[KCODES];      // zero-init; reset by finisher
__device__ float              g_sse;
__device__ int                g_done[NPT];
__device__ int                g_tiles_done;
__device__ unsigned long long g_best[NPT * TM];      // ~((dist_bits<<32)|k); 0 = identity

// ---- packed f32x2 helpers --------------------------------------------------
__device__ __forceinline__ unsigned long long pack2(float x, float y) {
    unsigned long long r;
    asm("mov.b64 %0, {%1, %2};" : "=l"(r) : "f"(x), "f"(y));
    return r;
}
__device__ __forceinline__ void fma2(unsigned long long& d,
                                     unsigned long long a,
                                     unsigned long long b) {
    asm("fma.rn.f32x2 %0, %1, %2, %0;" : "+l"(d) : "l"(a), "l"(b));
}
__device__ __forceinline__ float2 unpack2(unsigned long long v) {
    float2 f;
    asm("mov.b64 {%0, %1}, %2;" : "=f"(f.x), "=f"(f.y) : "l"(v));
    return f;
}

struct Sm {
    float z_s[D_DIM][TM + 4];     // 33792 B : z tile [d][p]
    float e_s[D_DIM][KC + 4];     // 33792 B : chunk [d][k]; zq stage aliases
    float e2c[KC];                //   512 B
    float z2_s[TM];               //   512 B
    float red_d[4][TM];           //  2048 B (4 code-groups after in-warp merge)
    int   red_i[4][TM];           //  2048 B
    int   idx_s[TM];              //   512 B
    int   cnt_s[KCODES];          //  4096 B
    int   flag, flag2;
};                                 // ~77.3 KB -> 2 CTAs/SM

__global__ void __launch_bounds__(256, 2)
vq_all(const float* __restrict__ ze, const float* __restrict__ cb,
       float* __restrict__ out) {
    extern __shared__ __align__(16) char smem_raw[];
    Sm* sm = reinterpret_cast<Sm*>(smem_raw);

    const int tid = threadIdx.x;
    const int q0  = (blockIdx.x * QTOT) / NCTA;
    const int q1  = ((blockIdx.x + 1) * QTOT) / NCTA;

    // warp geometry: 8 pcols x 4 krows per warp (warp tile 64px x 32codes)
    const int w    = tid >> 5;           // warp 0..7
    const int l    = tid & 31;           // lane
    const int pcol = (l & 7) | ((w & 1) << 3);     // 0..15
    const int krow = (l >> 3) | ((w >> 1) << 2);   // 0..15
    const int p0    = pcol * 8;
    const int kloc0 = krow * 8;
    const int k_st  = tid & 127;         // staging: warp-per-d-row, conflict-free
    const int h_st  = tid >> 7;

    int   cur_tile = -1, seg_chunks = 0, b = 0, hw0 = 0;
    float z2r[8];
    float bestd[8];
    int   besti[8];

    for (int q = q0;; ++q) {
        const int tile = (q < q1) ? (q >> 3) : -1;

        if (tile != cur_tile) {
            if (cur_tile >= 0) {
                // ---- segment flush: merge bests into g_best ----------------
                // lexicographic (dist,k) min is commutative: merge the 4
                // in-warp krows via shfl-xor 8 and 16, then 4 code-groups
                // (w>>1) via smem.
#pragma unroll
                for (int j = 0; j < 8; ++j) {
                    float od = __shfl_xor_sync(0xffffffffu, bestd[j], 8);
                    int   oi = __shfl_xor_sync(0xffffffffu, besti[j], 8);
                    if (od < bestd[j] || (od == bestd[j] && oi < besti[j])) {
                        bestd[j] = od; besti[j] = oi;
                    }
                    od = __shfl_xor_sync(0xffffffffu, bestd[j], 16);
                    oi = __shfl_xor_sync(0xffffffffu, besti[j], 16);
                    if (od < bestd[j] || (od == bestd[j] && oi < besti[j])) {
                        bestd[j] = od; besti[j] = oi;
                    }
                }
                if (l < 8) {                         // one lane per pcol
#pragma unroll
                    for (int j = 0; j < 8; ++j) {
                        sm->red_d[w >> 1][p0 + j] = bestd[j];
                        sm->red_i[w >> 1][p0 + j] = besti[j];
                    }
                }
                __syncthreads();
                if (tid < TM) {
                    float bd = sm->red_d[0][tid];
                    int   bi = sm->red_i[0][tid];
#pragma unroll
                    for (int w2 = 1; w2 < 4; ++w2) {
                        float d2 = sm->red_d[w2][tid];
                        int   i2 = sm->red_i[w2][tid];
                        if (d2 < bd || (d2 == bd && i2 < bi)) { bd = d2; bi = i2; }
                    }
                    // dist strictly > 0 -> float bits are order-preserving
                    unsigned long long pk =
                        ((unsigned long long)__float_as_uint(bd) << 32) | (unsigned)bi;
                    atomicMax(&g_best[cur_tile * TM + tid], ~pk);
                }
                __threadfence();
                if (tid == 0)
                    sm->flag = (atomicAdd(&g_done[cur_tile], seg_chunks)
                                + seg_chunks == 8);
                __syncthreads();

                if (sm->flag) {
                    // ============ tile epilogue (z_s still resident) =========
                    __threadfence();
                    for (int i = tid; i < KCODES; i += 256) sm->cnt_s[i] = 0;
                    __syncthreads();
                    if (tid < TM) {
                        unsigned long long raw =
                            *((volatile unsigned long long*)&g_best[cur_tile * TM + tid]);
                        int bi = (int)(unsigned)((~raw) & 0xFFFFFFFFull);
                        sm->idx_s[tid] = bi;
                        out[OFS_IDX + cur_tile * TM + tid] = (float)bi;
                        atomicAdd(&sm->cnt_s[bi], 1);
                    }
                    __syncthreads();
                    for (int i = tid; i < KCODES; i += 256) {
                        int c = sm->cnt_s[i];
                        if (c) atomicAdd(&g_counts[i], c);
                    }
                    {   // gather z_q, z_q_st (reference two roundings), SSE
                        int p = tid >> 1, h = tid & 1;
                        int ci = sm->idx_s[p];
                        const float4* crow = reinterpret_cast<const float4*>(
                                                 cb + (size_t)ci * D_DIM) + h * 8;
                        float ssel = 0.f;
#pragma unroll
                        for (int i = 0; i < 8; ++i) {
                            float4 v = crow[i];
                            int d0 = h * 32 + i * 4;
                            float vv[4] = {v.x, v.y, v.z, v.w};
#pragma unroll
                            for (int cc = 0; cc < 4; ++cc) {
                                int d = d0 + cc;
                                float zev  = sm->z_s[d][p];
                                float diff = vv[cc] - zev;       // fl(z_q - z_e)
                                ssel = fmaf(diff, diff, ssel);
                                sm->e_s[d][p] = zev + diff;      // fl(z_e + diff)
                            }
                        }
#pragma unroll
                        for (int o = 16; o; o >>= 1)
                            ssel += __shfl_xor_sync(0xffffffffu, ssel, o);
                        if ((tid & 31) == 0) atomicAdd(&g_sse, ssel);
                    }
                    __syncthreads();
                    {   // coalesced z_q_st store
                        float* zo = out + (size_t)b * D_DIM * HW + hw0;
                        for (int f = tid; f < D_DIM * TM; f += 256) {
                            int d = f >> 7, p = f & 127;
                            zo[d * HW + p] = sm->e_s[d][p];
                        }
                    }
                    __threadfence();
                    if (tid == 0)
                        sm->flag2 = (atomicAdd(&g_tiles_done, 1) == NPT - 1);
                    __syncthreads();

                    if (sm->flag2) {
                        // ============ finalize + state reset =================
                        __threadfence();
                        float hpart = 0.f;
                        for (int i = tid; i < KCODES; i += 256) {
                            int c = *((volatile int*)&g_counts[i]);
                            float u = (float)c / 32768.0f;
                            out[OFS_USAGE + i] = u;
                            hpart += u * logf(u + 1e-10f);
                        }
#pragma unroll
                        for (int o = 16; o; o >>= 1)
                            hpart += __shfl_xor_sync(0xffffffffu, hpart, o);
                        if ((tid & 31) == 0) sm->red_d[0][tid >> 5] = hpart;
                        __syncthreads();
                        if (tid == 0) {
                            float H = 0.f;
#pragma unroll
                            for (int w2 = 0; w2 < 8; ++w2) H += sm->red_d[0][w2];
                            out[OFS_PPL] = expf(-H);
                            float msse = *((volatile float*)&g_sse);
                            float m = msse / 2097152.0f;
                            out[OFS_LOSS] = m + 0.25f * m;
                        }
                        __syncthreads();
                        // reset module state for next graph replay
                        for (int i = tid; i < KCODES; i += 256) g_counts[i] = 0;
                        for (int i = tid; i < NPT; i += 256)    g_done[i] = 0;
                        for (int i = tid; i < NPT * TM; i += 256) g_best[i] = 0ull;
                        if (tid == 0) { g_sse = 0.f; g_tiles_done = 0; }
                    }
                }
                __syncthreads();   // epilogue done before z_s is overwritten
            }
            if (tile < 0) break;

            // ---- load new tile --------------------------------------------
            cur_tile  = tile;
            seg_chunks = 0;
            b   = tile >> 3;
            hw0 = (tile & 7) * TM;
            const float* zbase = ze + (size_t)b * D_DIM * HW + hw0;
            for (int f = tid; f < D_DIM * TM; f += 256) {
                int d = f >> 7, p = f & 127;
                sm->z_s[d][p] = zbase[d * HW + p];
            }
            __syncthreads();
            if (tid < TM) {                          // reference rounding
                float s = 0.f;
#pragma unroll
                for (int d = 0; d < D_DIM; ++d) {
                    float v = sm->z_s[d][tid];
                    s = fmaf(v, v, s);
                }
                sm->z2_s[tid] = s;
            }
            __syncthreads();
#pragma unroll
            for (int j = 0; j < 8; ++j) z2r[j] = sm->z2_s[p0 + j];
#pragma unroll
            for (int j = 0; j < 8; ++j) { bestd[j] = 3.4e38f; besti[j] = 0; }
        }

        // ---- process one chunk --------------------------------------------
        const int kb = (q & 7) * KC;

        {   // stage codebook chunk transposed [d][k] (conflict-free STS)
            const float4* src = reinterpret_cast<const float4*>(
                                    cb + (size_t)(kb + k_st) * D_DIM) + h_st * 8;
#pragma unroll
            for (int i = 0; i < 8; ++i) {
                float4 v = src[i];
                int d0 = h_st * 32 + i * 4;
                sm->e_s[d0 + 0][k_st] = v.x;
                sm->e_s[d0 + 1][k_st] = v.y;
                sm->e_s[d0 + 2][k_st] = v.z;
                sm->e_s[d0 + 3][k_st] = v.w;
            }
        }
        __syncthreads();
        if (tid < KC) {                              // inline e2, reference order
            float s = 0.f;
#pragma unroll
            for (int d = 0; d < D_DIM; ++d) {
                float v = sm->e_s[d][tid];
                s = fmaf(v, v, s);
            }
            sm->e2c[tid] = s;
        }
        __syncthreads();

        unsigned long long acc[8][4];
#pragma unroll
        for (int j = 0; j < 8; ++j)
#pragma unroll
            for (int kk = 0; kk < 4; ++kk) acc[j][kk] = 0ull;

#pragma unroll 16
        for (int d = 0; d < D_DIM; ++d) {
            ulonglong2 eA = *reinterpret_cast<const ulonglong2*>(&sm->e_s[d][kloc0]);
            ulonglong2 eB = *reinterpret_cast<const ulonglong2*>(&sm->e_s[d][kloc0 + 4]);
            float4 za = *reinterpret_cast<const float4*>(&sm->z_s[d][p0]);
            float4 zb = *reinterpret_cast<const float4*>(&sm->z_s[d][p0 + 4]);
            float zr[8] = {za.x, za.y, za.z, za.w, zb.x, zb.y, zb.z, zb.w};
#pragma unroll
            for (int j = 0; j < 8; ++j) {
                unsigned long long zz = pack2(zr[j], zr[j]);
                fma2(acc[j][0], zz, eA.x);
                fma2(acc[j][1], zz, eA.y);
                fma2(acc[j][2], zz, eB.x);
                fma2(acc[j][3], zz, eB.y);
            }
        }

        float e2r[8];
#pragma unroll
        for (int kk = 0; kk < 8; ++kk) e2r[kk] = sm->e2c[kloc0 + kk];
#pragma unroll
        for (int j = 0; j < 8; ++j) {
            float a = z2r[j];
#pragma unroll
            for (int kk = 0; kk < 4; ++kk) {
                float2 s = unpack2(acc[j][kk]);
                float d0 = fmaf(-2.f, s.x, a + e2r[kk * 2]);
                float d1 = fmaf(-2.f, s.y, a + e2r[kk * 2 + 1]);
                int k0 = kb + kloc0 + kk * 2;
                if (d0 < bestd[j]) { bestd[j] = d0; besti[j] = k0; }
                if (d1 < bestd[j]) { bestd[j] = d1; besti[j] = k0 + 1; }
            }
        }
        ++seg_chunks;
        __syncthreads();   // all reads of e_s done before next stage/epilogue
    }
}

// ---------------------------------------------------------------------------
extern "C" void kernel_launch(void* const* d_in, const int* in_sizes, int n_in,
                              void* d_out, int out_size) {
    const float* a0 = (const float*)d_in[0];
    const float* a1 = (const float*)d_in[1];
    const float* ze = a0;
    const float* cb = a1;
    if (n_in >= 2 && in_sizes[0] == KCODES * D_DIM) { ze = a1; cb = a0; }
    float* out = (float*)d_out;

    static_assert(sizeof(Sm) < 100 * 1024, "smem too big");
    cudaFuncSetAttribute(vq_all, cudaFuncAttributeMaxDynamicSharedMemorySize,
                         (int)sizeof(Sm));
    vq_all<<<NCTA, 256, sizeof(Sm)>>>(ze, cb, out);
}

// round 15
// speedup vs baseline: 1.5668x; 1.0379x over previous
#include <cuda_runtime.h>
#include <math.h>
#include <stdint.h>

// ---------------------------------------------------------------------------
// VQ-VAE VectorQuantizer forward — single persistent kernel (R10 skeleton).
// R15: conflict-free z layout — pixel p stored at float offset p + (p>>5)*4
// (pitch 140). Quarter-warp z LDS.128 now hits all 32 banks once: z phases
// halve, crossbar (the measured binding unit) drops from 1.5x fma to parity.
//   out = [ z_q_st (2097152) | vq_loss | indices (32768) | perplexity | usage (1024) ]
// ---------------------------------------------------------------------------

#define D_DIM   64
#define KCODES  1024
#define HW      1024
#define TM      128
#define KC      128
#define NPT     256                 // pixel tiles
#define QTOT    2048                // 256 tiles x 8 chunks
#define NCTA    296                 // 2 per SM on 148 SMs
#define ZPITCH  140                 // 128 px + 4-float pad per 32-px group

#define OFS_LOSS  2097152
#define OFS_IDX   2097153
#define OFS_PPL   2129921
#define OFS_USAGE 2129922

__device__ int                g_counts[KCODES];      // zero-init; reset by finisher
__device__ float              g_sse;
__device__ int                g_done[NPT];
__device__ int                g_tiles_done;
__device__ unsigned long long g_best[NPT * TM];      // ~((dist_bits<<32)|k); 0 = identity

// ---- packed f32x2 helpers --------------------------------------------------
__device__ __forceinline__ unsigned long long pack2(float x, float y) {
    unsigned long long r;
    asm("mov.b64 %0, {%1, %2};" : "=l"(r) : "f"(x), "f"(y));
    return r;
}
__device__ __forceinline__ void fma2(unsigned long long& d,
                                     unsigned long long a,
                                     unsigned long long b) {
    asm("fma.rn.f32x2 %0, %1, %2, %0;" : "+l"(d) : "l"(a), "l"(b));
}
__device__ __forceinline__ float2 unpack2(unsigned long long v) {
    float2 f;
    asm("mov.b64 {%0, %1}, %2;" : "=f"(f.x), "=f"(f.y) : "l"(v));
    return f;
}
__device__ __forceinline__ int zoff(int p) {         // conflict-free z offset
    return p + ((p >> 5) << 2);
}

struct Sm {
    float z_s[D_DIM][ZPITCH];     // 35840 B : z tile [d][zoff(p)]
    float e_s[D_DIM][KC + 4];     // 33792 B : chunk [d][k]; zq stage aliases
    float e2c[KC];                //   512 B
    float z2_s[TM];               //   512 B
    float red_d[8][TM];           //  4096 B
    int   red_i[8][TM];           //  4096 B
    int   idx_s[TM];              //   512 B
    int   cnt_s[KCODES];          //  4096 B
    int   flag, flag2;
};                                 // ~83.3 KB -> 2 CTAs/SM

__global__ void __launch_bounds__(256, 2)
vq_all(const float* __restrict__ ze, const float* __restrict__ cb,
       float* __restrict__ out) {
    extern __shared__ __align__(16) char smem_raw[];
    Sm* sm = reinterpret_cast<Sm*>(smem_raw);

    const int tid = threadIdx.x;
    const int q0  = (blockIdx.x * QTOT) / NCTA;
    const int q1  = ((blockIdx.x + 1) * QTOT) / NCTA;

    const int pcol  = tid & 15;
    const int krow  = tid >> 4;
    const int p0    = pcol * 8;
    const int zp0   = zoff(p0);          // za at zp0, zb at zp0+4 (same group)
    const int kloc0 = krow * 8;
    const int k_st  = tid & 127;         // staging: warp-per-d-row, conflict-free
    const int h_st  = tid >> 7;

    int   cur_tile = -1, seg_chunks = 0, b = 0, hw0 = 0;
    float z2r[8];
    float bestd[8];
    int   besti[8];

    for (int q = q0;; ++q) {
        const int tile = (q < q1) ? (q >> 3) : -1;

        if (tile != cur_tile) {
            if (cur_tile >= 0) {
                // ---- segment flush: merge bests into g_best ----------------
#pragma unroll
                for (int j = 0; j < 8; ++j) {
                    float od = __shfl_xor_sync(0xffffffffu, bestd[j], 16);
                    int   oi = __shfl_xor_sync(0xffffffffu, besti[j], 16);
                    if (od < bestd[j] || (od == bestd[j] && oi < besti[j])) {
                        bestd[j] = od; besti[j] = oi;
                    }
                }
                const int w = tid >> 5;
                if ((tid & 16) == 0) {
#pragma unroll
                    for (int j = 0; j < 8; ++j) {
                        sm->red_d[w][p0 + j] = bestd[j];
                        sm->red_i[w][p0 + j] = besti[j];
                    }
                }
                __syncthreads();
                if (tid < TM) {
                    float bd = sm->red_d[0][tid];
                    int   bi = sm->red_i[0][tid];
#pragma unroll
                    for (int w2 = 1; w2 < 8; ++w2) {
                        float d2 = sm->red_d[w2][tid];
                        int   i2 = sm->red_i[w2][tid];
                        if (d2 < bd || (d2 == bd && i2 < bi)) { bd = d2; bi = i2; }
                    }
                    // dist strictly > 0 -> float bits are order-preserving
                    unsigned long long pk =
                        ((unsigned long long)__float_as_uint(bd) << 32) | (unsigned)bi;
                    atomicMax(&g_best[cur_tile * TM + tid], ~pk);
                }
                __threadfence();
                if (tid == 0)
                    sm->flag = (atomicAdd(&g_done[cur_tile], seg_chunks)
                                + seg_chunks == 8);
                __syncthreads();

                if (sm->flag) {
                    // ============ tile epilogue (z_s still resident) =========
                    __threadfence();
                    for (int i = tid; i < KCODES; i += 256) sm->cnt_s[i] = 0;
                    __syncthreads();
                    if (tid < TM) {
                        unsigned long long raw =
                            *((volatile unsigned long long*)&g_best[cur_tile * TM + tid]);
                        int bi = (int)(unsigned)((~raw) & 0xFFFFFFFFull);
                        sm->idx_s[tid] = bi;
                        out[OFS_IDX + cur_tile * TM + tid] = (float)bi;
                        atomicAdd(&sm->cnt_s[bi], 1);
                    }
                    __syncthreads();
                    for (int i = tid; i < KCODES; i += 256) {
                        int c = sm->cnt_s[i];
                        if (c) atomicAdd(&g_counts[i], c);
                    }
                    {   // gather z_q, z_q_st (reference two roundings), SSE
                        int p = tid >> 1, h = tid & 1;
                        int ci = sm->idx_s[p];
                        const float4* crow = reinterpret_cast<const float4*>(
                                                 cb + (size_t)ci * D_DIM) + h * 8;
                        float ssel = 0.f;
                        const int zp = zoff(p);
#pragma unroll
                        for (int i = 0; i < 8; ++i) {
                            float4 v = crow[i];
                            int d0 = h * 32 + i * 4;
                            float vv[4] = {v.x, v.y, v.z, v.w};
#pragma unroll
                            for (int cc = 0; cc < 4; ++cc) {
                                int d = d0 + cc;
                                float zev  = sm->z_s[d][zp];
                                float diff = vv[cc] - zev;       // fl(z_q - z_e)
                                ssel = fmaf(diff, diff, ssel);
                                sm->e_s[d][p] = zev + diff;      // fl(z_e + diff)
                            }
                        }
#pragma unroll
                        for (int o = 16; o; o >>= 1)
                            ssel += __shfl_xor_sync(0xffffffffu, ssel, o);
                        if ((tid & 31) == 0) atomicAdd(&g_sse, ssel);
                    }
                    __syncthreads();
                    {   // coalesced z_q_st store
                        float* zo = out + (size_t)b * D_DIM * HW + hw0;
                        for (int f = tid; f < D_DIM * TM; f += 256) {
                            int d = f >> 7, p = f & 127;
                            zo[d * HW + p] = sm->e_s[d][p];
                        }
                    }
                    __threadfence();
                    if (tid == 0)
                        sm->flag2 = (atomicAdd(&g_tiles_done, 1) == NPT - 1);
                    __syncthreads();

                    if (sm->flag2) {
                        // ============ finalize + state reset =================
                        __threadfence();
                        float hpart = 0.f;
                        for (int i = tid; i < KCODES; i += 256) {
                            int c = *((volatile int*)&g_counts[i]);
                            float u = (float)c / 32768.0f;
                            out[OFS_USAGE + i] = u;
                            hpart += u * logf(u + 1e-10f);
                        }
#pragma unroll
                        for (int o = 16; o; o >>= 1)
                            hpart += __shfl_xor_sync(0xffffffffu, hpart, o);
                        if ((tid & 31) == 0) sm->red_d[0][tid >> 5] = hpart;
                        __syncthreads();
                        if (tid == 0) {
                            float H = 0.f;
#pragma unroll
                            for (int w2 = 0; w2 < 8; ++w2) H += sm->red_d[0][w2];
                            out[OFS_PPL] = expf(-H);
                            float msse = *((volatile float*)&g_sse);
                            float m = msse / 2097152.0f;
                            out[OFS_LOSS] = m + 0.25f * m;
                        }
                        __syncthreads();
                        // reset module state for next graph replay
                        for (int i = tid; i < KCODES; i += 256) g_counts[i] = 0;
                        for (int i = tid; i < NPT; i += 256)    g_done[i] = 0;
                        for (int i = tid; i < NPT * TM; i += 256) g_best[i] = 0ull;
                        if (tid == 0) { g_sse = 0.f; g_tiles_done = 0; }
                    }
                }
                __syncthreads();   // epilogue done before z_s is overwritten
            }
            if (tile < 0) break;

            // ---- load new tile --------------------------------------------
            cur_tile  = tile;
            seg_chunks = 0;
            b   = tile >> 3;
            hw0 = (tile & 7) * TM;
            const float* zbase = ze + (size_t)b * D_DIM * HW + hw0;
            for (int f = tid; f < D_DIM * TM; f += 256) {
                int d = f >> 7, p = f & 127;
                sm->z_s[d][zoff(p)] = zbase[d * HW + p];
            }
            __syncthreads();
            if (tid < TM) {                          // reference rounding
                float s = 0.f;
                const int zp = zoff(tid);
#pragma unroll
                for (int d = 0; d < D_DIM; ++d) {
                    float v = sm->z_s[d][zp];
                    s = fmaf(v, v, s);
                }
                sm->z2_s[tid] = s;
            }
            __syncthreads();
#pragma unroll
            for (int j = 0; j < 8; ++j) z2r[j] = sm->z2_s[p0 + j];
#pragma unroll
            for (int j = 0; j < 8; ++j) { bestd[j] = 3.4e38f; besti[j] = 0; }
        }

        // ---- process one chunk --------------------------------------------
        const int kb = (q & 7) * KC;

        {   // stage codebook chunk transposed [d][k] (conflict-free STS)
            const float4* src = reinterpret_cast<const float4*>(
                                    cb + (size_t)(kb + k_st) * D_DIM) + h_st * 8;
#pragma unroll
            for (int i = 0; i < 8; ++i) {
                float4 v = src[i];
                int d0 = h_st * 32 + i * 4;
                sm->e_s[d0 + 0][k_st] = v.x;
                sm->e_s[d0 + 1][k_st] = v.y;
                sm->e_s[d0 + 2][k_st] = v.z;
                sm->e_s[d0 + 3][k_st] = v.w;
            }
        }
        __syncthreads();
        if (tid < KC) {                              // inline e2, reference order
            float s = 0.f;
#pragma unroll
            for (int d = 0; d < D_DIM; ++d) {
                float v = sm->e_s[d][tid];
                s = fmaf(v, v, s);
            }
            sm->e2c[tid] = s;
        }
        __syncthreads();

        unsigned long long acc[8][4];
#pragma unroll
        for (int j = 0; j < 8; ++j)
#pragma unroll
            for (int kk = 0; kk < 4; ++kk) acc[j][kk] = 0ull;

#pragma unroll 16
        for (int d = 0; d < D_DIM; ++d) {
            ulonglong2 eA = *reinterpret_cast<const ulonglong2*>(&sm->e_s[d][kloc0]);
            ulonglong2 eB = *reinterpret_cast<const ulonglong2*>(&sm->e_s[d][kloc0 + 4]);
            float4 za = *reinterpret_cast<const float4*>(&sm->z_s[d][zp0]);
            float4 zb = *reinterpret_cast<const float4*>(&sm->z_s[d][zp0 + 4]);
            float zr[8] = {za.x, za.y, za.z, za.w, zb.x, zb.y, zb.z, zb.w};
#pragma unroll
            for (int j = 0; j < 8; ++j) {
                unsigned long long zz = pack2(zr[j], zr[j]);
                fma2(acc[j][0], zz, eA.x);
                fma2(acc[j][1], zz, eA.y);
                fma2(acc[j][2], zz, eB.x);
                fma2(acc[j][3], zz, eB.y);
            }
        }

        float e2r[8];
#pragma unroll
        for (int kk = 0; kk < 8; ++kk) e2r[kk] = sm->e2c[kloc0 + kk];
#pragma unroll
        for (int j = 0; j < 8; ++j) {
            float a = z2r[j];
#pragma unroll
            for (int kk = 0; kk < 4; ++kk) {
                float2 s = unpack2(acc[j][kk]);
                float d0 = fmaf(-2.f, s.x, a + e2r[kk * 2]);
                float d1 = fmaf(-2.f, s.y, a + e2r[kk * 2 + 1]);
                int k0 = kb + kloc0 + kk * 2;
                if (d0 < bestd[j]) { bestd[j] = d0; besti[j] = k0; }
                if (d1 < bestd[j]) { bestd[j] = d1; besti[j] = k0 + 1; }
            }
        }
        ++seg_chunks;
        __syncthreads();   // all reads of e_s done before next stage/epilogue
    }
}

// ---------------------------------------------------------------------------
extern "C" void kernel_launch(void* const* d_in, const int* in_sizes, int n_in,
                              void* d_out, int out_size) {
    const float* a0 = (const float*)d_in[0];
    const float* a1 = (const float*)d_in[1];
    const float* ze = a0;
    const float* cb = a1;
    if (n_in >= 2 && in_sizes[0] == KCODES * D_DIM) { ze = a1; cb = a0; }
    float* out = (float*)d_out;

    static_assert(sizeof(Sm) < 100 * 1024, "smem too big");
    cudaFuncSetAttribute(vq_all, cudaFuncAttributeMaxDynamicSharedMemorySize,
                         (int)sizeof(Sm));
    vq_all<<<NCTA, 256, sizeof(Sm)>>>(ze, cb, out);
}